// round 11
// baseline (speedup 1.0000x reference)
#include <cuda_runtime.h>
#include <cuda_bf16.h>
#include <cstdint>

// ---------------------------------------------------------------------------
// ResidualGatedGCN — node tf32 GEMM + PERSISTENT fused edge GEMM/scatter
//   - We staged to SMEM once per persistent CTA
//   - gated scatter computed directly from MMA accumulator fragments
//   - cross-tile cp.async pipeline (phase C overlaps next tile's A loads)
// ---------------------------------------------------------------------------

#define N_NODES 50000
#define N_EDGES 600000
#define NTILES  ((N_EDGES + 127) / 128)

__device__ float g_qkv[(size_t)N_NODES * 384];      // 76.8 MB

#define KC      32
#define APAD    36
#define BPAD    132
#define A_CHUNK_BYTES (128 * APAD * 4)   // 18432
#define B_BYTES       (128 * BPAD * 4)   // 67584
#define GEMM_SMEM     (B_BYTES + 2 * A_CHUNK_BYTES)        // 104448
#define FUSED_SMEM    (GEMM_SMEM + 2 * 128 * 4)

__device__ __forceinline__ uint32_t f2tf32(float f) {
    uint32_t u;
    asm("cvt.rna.tf32.f32 %0, %1;" : "=r"(u) : "f"(f));
    return u;
}
__device__ __forceinline__ void mma_tf32(float& d0, float& d1, float& d2, float& d3,
                                         uint32_t a0, uint32_t a1, uint32_t a2, uint32_t a3,
                                         uint32_t b0, uint32_t b1)
{
    asm volatile(
        "mma.sync.aligned.m16n8k8.row.col.f32.tf32.tf32.f32 "
        "{%0,%1,%2,%3}, {%4,%5,%6,%7}, {%8,%9}, {%0,%1,%2,%3};"
        : "+f"(d0), "+f"(d1), "+f"(d2), "+f"(d3)
        : "r"(a0), "r"(a1), "r"(a2), "r"(a3), "r"(b0), "r"(b1));
}
__device__ __forceinline__ uint32_t smem_u32(const void* p) {
    uint32_t a;
    asm("{ .reg .u64 t; cvta.to.shared.u64 t, %1; cvt.u32.u64 %0, t; }"
        : "=r"(a) : "l"(p));
    return a;
}
__device__ __forceinline__ uint64_t policy_evict_first() {
    uint64_t pol;
    asm("createpolicy.fractional.L2::evict_first.b64 %0, 1.0;" : "=l"(pol));
    return pol;
}
__device__ __forceinline__ uint64_t policy_evict_last() {
    uint64_t pol;
    asm("createpolicy.fractional.L2::evict_last.b64 %0, 1.0;" : "=l"(pol));
    return pol;
}
__device__ __forceinline__ void cp_async16_pol(uint32_t sdst, const void* gsrc,
                                               int bytes, uint64_t pol) {
    asm volatile("cp.async.cg.shared.global.L2::cache_hint [%0], [%1], 16, %2, %3;"
                 :: "r"(sdst), "l"(gsrc), "r"(bytes), "l"(pol));
}
__device__ __forceinline__ void cp_commit() {
    asm volatile("cp.async.commit_group;" ::: "memory");
}
__device__ __forceinline__ void cp_wait1() {
    asm volatile("cp.async.wait_group 1;" ::: "memory");
}
__device__ __forceinline__ void cp_wait0() {
    asm volatile("cp.async.wait_group 0;" ::: "memory");
}
__device__ __forceinline__ float2 ld_keep_f2(const float* p, uint64_t pol) {
    float2 v;
    asm volatile("ld.global.nc.L2::cache_hint.v2.f32 {%0,%1}, [%2], %3;"
                 : "=f"(v.x), "=f"(v.y) : "l"(p), "l"(pol));
    return v;
}
__device__ __forceinline__ float sigmoidf_(float x) {
    return 1.0f / (1.0f + __expf(-x));
}
__device__ __forceinline__ void red_v2(float* p, float x, float y) {
    asm volatile("red.global.add.v2.f32 [%0], {%1,%2};"
                 :: "l"(p), "f"(x), "f"(y));
}

struct GemmCtx { int wid, lane, g, t, wm, wn; };

// ===========================================================================
// Node GEMM (unchanged from R10): 128x128 tile, K=128, cp.async pipeline.
// ===========================================================================
__device__ __forceinline__
void gemm_body(const float* __restrict__ A, int M, int Wstride,
               const float* __restrict__ W, int colW0,
               int row0, char* smem, const GemmCtx& cx,
               float acc[2][8][4], uint64_t pol)
{
    uint32_t* Bs = (uint32_t*)smem;
    float* Abuf[2] = { (float*)(smem + B_BYTES),
                       (float*)(smem + B_BYTES + A_CHUNK_BYTES) };
    const uint32_t sbase = smem_u32(smem);
    const uint32_t a_s[2] = { sbase + B_BYTES, sbase + B_BYTES + A_CHUNK_BYTES };
    const int tid = threadIdx.x;

    auto copyA = [&](int chunk, uint32_t sdst) {
        #pragma unroll
        for (int j = 0; j < 4; j++) {
            const int idx = tid + j * 256;
            const int r   = idx >> 3;
            const int seg = idx & 7;
            const int gr  = row0 + r;
            const int bytes = (gr < M) ? 16 : 0;
            const int grc = (gr < M) ? gr : (M - 1);
            cp_async16_pol(sdst + (r * APAD + seg * 4) * 4,
                           A + (size_t)grc * 128 + chunk * KC + seg * 4, bytes, pol);
        }
    };

    copyA(0, a_s[0]); cp_commit();

    #pragma unroll
    for (int it = 0; it < 16; it++) {
        const int idx = tid + it * 256;
        const int k   = idx >> 5;
        const int n4  = (idx & 31) * 4;
        const float4 v = *(const float4*)&W[(size_t)k * Wstride + colW0 + n4];
        uint4 o;
        o.x = f2tf32(v.x); o.y = f2tf32(v.y); o.z = f2tf32(v.z); o.w = f2tf32(v.w);
        *(uint4*)&Bs[k * BPAD + n4] = o;
    }

    copyA(1, a_s[1]); cp_commit();

    #pragma unroll
    for (int m = 0; m < 2; m++)
        #pragma unroll
        for (int n = 0; n < 8; n++)
            #pragma unroll
            for (int j = 0; j < 4; j++) acc[m][n][j] = 0.f;

    auto compute_chunk = [&](const float* __restrict__ Ab, int kb) {
        #pragma unroll
        for (int ks = 0; ks < 4; ks++) {
            const int k0 = ks * 8;
            uint32_t af[2][4];
            #pragma unroll
            for (int m = 0; m < 2; m++) {
                const int rb = cx.wm * 32 + m * 16 + cx.g;
                const float* p0 = Ab + rb * APAD + k0 + cx.t;
                const float* p1 = Ab + (rb + 8) * APAD + k0 + cx.t;
                af[m][0] = f2tf32(p0[0]);
                af[m][1] = f2tf32(p1[0]);
                af[m][2] = f2tf32(p0[4]);
                af[m][3] = f2tf32(p1[4]);
            }
            #pragma unroll
            for (int n = 0; n < 8; n++) {
                const int nidx = cx.wn * 64 + n * 8 + cx.g;
                const uint32_t b0 = Bs[(kb + k0 + cx.t) * BPAD + nidx];
                const uint32_t b1 = Bs[(kb + k0 + cx.t + 4) * BPAD + nidx];
                #pragma unroll
                for (int m = 0; m < 2; m++)
                    mma_tf32(acc[m][n][0], acc[m][n][1], acc[m][n][2], acc[m][n][3],
                             af[m][0], af[m][1], af[m][2], af[m][3], b0, b1);
            }
        }
    };

    cp_wait1(); __syncthreads();
    compute_chunk(Abuf[0], 0);
    __syncthreads(); copyA(2, a_s[0]); cp_commit();

    cp_wait1(); __syncthreads();
    compute_chunk(Abuf[1], 32);
    __syncthreads(); copyA(3, a_s[1]); cp_commit();

    cp_wait1(); __syncthreads();
    compute_chunk(Abuf[0], 64);

    cp_wait0(); __syncthreads();
    compute_chunk(Abuf[1], 96);
}

__global__ __launch_bounds__(256, 2)
void node_gemm(const float* __restrict__ nf,
               const float* __restrict__ Wk,
               const float* __restrict__ Wb,
               float* __restrict__ out,
               float* __restrict__ qkv)
{
    extern __shared__ char smem[];
    const int row0  = blockIdx.y * 128;
    const int colW0 = blockIdx.x * 128;
    const uint64_t pol = policy_evict_first();

    GemmCtx cx;
    {
        const int tid = threadIdx.x;
        cx.wid = tid >> 5; cx.lane = tid & 31;
        cx.g = cx.lane >> 2; cx.t = cx.lane & 3;
        cx.wm = cx.wid >> 1; cx.wn = cx.wid & 1;
    }
    float acc[2][8][4];
    gemm_body(nf, N_NODES, 512, Wk, colW0, row0, smem, cx, acc, pol);

    float2 bvs[8];
    #pragma unroll
    for (int n = 0; n < 8; n++)
        bvs[n] = *(const float2*)&Wb[colW0 + cx.wn * 64 + n * 8 + 2 * cx.t];

    float* C;
    int Cstride, colC0;
    if (blockIdx.x == 0) { C = out; Cstride = 128; colC0 = 0; }
    else                 { C = qkv; Cstride = 384; colC0 = colW0 - 128; }

    #pragma unroll
    for (int m = 0; m < 2; m++) {
        const int r0 = row0 + cx.wm * 32 + m * 16 + cx.g;
        const int r1 = r0 + 8;
        #pragma unroll
        for (int n = 0; n < 8; n++) {
            const int cc = colC0 + cx.wn * 64 + n * 8 + 2 * cx.t;
            if (r0 < N_NODES)
                *(float2*)&C[(size_t)r0 * Cstride + cc] =
                    make_float2(acc[m][n][0] + bvs[n].x, acc[m][n][1] + bvs[n].y);
            if (r1 < N_NODES)
                *(float2*)&C[(size_t)r1 * Cstride + cc] =
                    make_float2(acc[m][n][2] + bvs[n].x, acc[m][n][3] + bvs[n].y);
        }
    }
}

// ===========================================================================
// Persistent fused edge kernel. B (We) staged once; per tile:
// cp.async-pipelined A GEMM -> scatter straight from acc fragments.
// ===========================================================================
__global__ __launch_bounds__(256, 2)
void edge_fused(const float* __restrict__ ef,
                const float* __restrict__ We,
                const float* __restrict__ Web,
                const int*   __restrict__ snd,
                const int*   __restrict__ rcv,
                const float* __restrict__ qkv,
                float* __restrict__ out)
{
    extern __shared__ char smem[];
    uint32_t* Bs = (uint32_t*)smem;
    float* Abuf[2] = { (float*)(smem + B_BYTES),
                       (float*)(smem + B_BYTES + A_CHUNK_BYTES) };
    int* s_snd = (int*)(smem + GEMM_SMEM);
    int* s_rcv = (int*)(smem + GEMM_SMEM + 128 * 4);
    const uint32_t sbase = smem_u32(smem);
    const uint32_t a_s[2] = { sbase + B_BYTES, sbase + B_BYTES + A_CHUNK_BYTES };

    const int tid = threadIdx.x;
    const uint64_t pol_stream = policy_evict_first();
    const uint64_t pol_keep   = policy_evict_last();

    GemmCtx cx;
    cx.wid = tid >> 5; cx.lane = tid & 31;
    cx.g = cx.lane >> 2; cx.t = cx.lane & 3;
    cx.wm = cx.wid >> 1; cx.wn = cx.wid & 1;

    auto copyA = [&](int tile, int chunk, uint32_t sdst) {
        const int row0 = tile * 128;
        #pragma unroll
        for (int j = 0; j < 4; j++) {
            const int idx = tid + j * 256;
            const int r   = idx >> 3;
            const int seg = idx & 7;
            const int gr  = row0 + r;
            const int bytes = (gr < N_EDGES) ? 16 : 0;
            const int grc = (gr < N_EDGES) ? gr : (N_EDGES - 1);
            cp_async16_pol(sdst + (r * APAD + seg * 4) * 4,
                           ef + (size_t)grc * 128 + chunk * KC + seg * 4, bytes, pol_stream);
        }
    };

    // ---- stage B (We) ONCE per persistent CTA ----
    #pragma unroll
    for (int it = 0; it < 16; it++) {
        const int idx = tid + it * 256;
        const int k   = idx >> 5;
        const int n4  = (idx & 31) * 4;
        const float4 v = *(const float4*)&We[(size_t)k * 128 + n4];
        uint4 o;
        o.x = f2tf32(v.x); o.y = f2tf32(v.y); o.z = f2tf32(v.z); o.w = f2tf32(v.w);
        *(uint4*)&Bs[k * BPAD + n4] = o;
    }

    float2 bvs[8];
    #pragma unroll
    for (int n = 0; n < 8; n++)
        bvs[n] = *(const float2*)&Web[cx.wn * 64 + n * 8 + 2 * cx.t];

    auto compute_chunk = [&](const float* __restrict__ Ab, int kb, float acc[2][8][4]) {
        #pragma unroll
        for (int ks = 0; ks < 4; ks++) {
            const int k0 = ks * 8;
            uint32_t af[2][4];
            #pragma unroll
            for (int m = 0; m < 2; m++) {
                const int rb = cx.wm * 32 + m * 16 + cx.g;
                const float* p0 = Ab + rb * APAD + k0 + cx.t;
                const float* p1 = Ab + (rb + 8) * APAD + k0 + cx.t;
                af[m][0] = f2tf32(p0[0]);
                af[m][1] = f2tf32(p1[0]);
                af[m][2] = f2tf32(p0[4]);
                af[m][3] = f2tf32(p1[4]);
            }
            #pragma unroll
            for (int n = 0; n < 8; n++) {
                const int nidx = cx.wn * 64 + n * 8 + cx.g;
                const uint32_t b0 = Bs[(kb + k0 + cx.t) * BPAD + nidx];
                const uint32_t b1 = Bs[(kb + k0 + cx.t + 4) * BPAD + nidx];
                #pragma unroll
                for (int m = 0; m < 2; m++)
                    mma_tf32(acc[m][n][0], acc[m][n][1], acc[m][n][2], acc[m][n][3],
                             af[m][0], af[m][1], af[m][2], af[m][3], b0, b1);
            }
        }
    };

    int tile = blockIdx.x;
    if (tile < NTILES) {
        copyA(tile, 0, a_s[0]); cp_commit();
        copyA(tile, 1, a_s[1]); cp_commit();
    }

    for (; tile < NTILES; tile += gridDim.x) {
        const int row0 = tile * 128;
        const int nxt  = tile + gridDim.x;
        const bool has_next = (nxt < NTILES);

        __syncthreads();   // previous phase C done before re-staging indices
        if (tid < 128) {
            const int e = row0 + tid;
            s_snd[tid] = (e < N_EDGES) ? __ldg(&snd[e]) : 0;
        } else {
            const int e = row0 + tid - 128;
            s_rcv[tid - 128] = (e < N_EDGES) ? __ldg(&rcv[e]) : 0;
        }

        float acc[2][8][4];
        #pragma unroll
        for (int m = 0; m < 2; m++)
            #pragma unroll
            for (int n = 0; n < 8; n++)
                #pragma unroll
                for (int j = 0; j < 4; j++) acc[m][n][j] = 0.f;

        cp_wait1(); __syncthreads();
        compute_chunk(Abuf[0], 0, acc);
        __syncthreads(); copyA(tile, 2, a_s[0]); cp_commit();

        cp_wait1(); __syncthreads();
        compute_chunk(Abuf[1], 32, acc);
        __syncthreads(); copyA(tile, 3, a_s[1]); cp_commit();

        cp_wait1(); __syncthreads();
        compute_chunk(Abuf[0], 64, acc);
        __syncthreads();
        if (has_next) { copyA(nxt, 0, a_s[0]); cp_commit(); }

        if (has_next) cp_wait1(); else cp_wait0();
        __syncthreads();
        compute_chunk(Abuf[1], 96, acc);
        __syncthreads();
        if (has_next) { copyA(nxt, 1, a_s[1]); cp_commit(); }

        // ---- phase C: scatter straight from acc fragments ----
        // thread (wm,g) owns edge rows wm*32 + m*16 + g (+8); cols wn*64+n*8+2t.
        const int colbase = cx.wn * 64 + 2 * cx.t;
        #pragma unroll
        for (int m = 0; m < 2; m++) {
            #pragma unroll
            for (int rsel = 0; rsel < 2; rsel++) {
                const int el = cx.wm * 32 + m * 16 + cx.g + rsel * 8;
                const bool ok = (row0 + el) < N_EDGES;
                const int s = s_snd[el];
                const int r = s_rcv[el];
                const float* bq = qkv + (size_t)r * 384 + colbase;
                const float* bk = qkv + (size_t)s * 384 + 128 + colbase;
                const float* bv = qkv + (size_t)s * 384 + 256 + colbase;

                float2 q[8], kk[8], vv[8];
                #pragma unroll
                for (int n = 0; n < 8; n++) q[n]  = ld_keep_f2(bq + n * 8, pol_keep);
                #pragma unroll
                for (int n = 0; n < 8; n++) kk[n] = ld_keep_f2(bk + n * 8, pol_keep);
                #pragma unroll
                for (int n = 0; n < 8; n++) vv[n] = ld_keep_f2(bv + n * 8, pol_keep);

                float* ob = out + (size_t)r * 128 + colbase;
                #pragma unroll
                for (int n = 0; n < 8; n++) {
                    const float e0 = acc[m][n][rsel * 2 + 0] + bvs[n].x;
                    const float e1 = acc[m][n][rsel * 2 + 1] + bvs[n].y;
                    const float mx = sigmoidf_(q[n].x + kk[n].x + e0) * vv[n].x;
                    const float my = sigmoidf_(q[n].y + kk[n].y + e1) * vv[n].y;
                    if (ok) red_v2(ob + n * 8, mx, my);
                }
            }
        }
    }
}

// ---------------------------------------------------------------------------
// Launch
// Inputs: 0 nf[50000,128] 1 snd[600000] 2 rcv[600000] 3 ef[600000,128]
//         4 Wk[128,512] 5 Wb[512] 6 Wek[128,128] 7 Web[128]
// ---------------------------------------------------------------------------
extern "C" void kernel_launch(void* const* d_in, const int* in_sizes, int n_in,
                              void* d_out, int out_size)
{
    const float* nf   = (const float*)d_in[0];
    const int*   snd  = (const int*)  d_in[1];
    const int*   rcv  = (const int*)  d_in[2];
    const float* ef   = (const float*)d_in[3];
    const float* Wk   = (const float*)d_in[4];
    const float* Wb   = (const float*)d_in[5];
    const float* Wek  = (const float*)d_in[6];
    const float* Web  = (const float*)d_in[7];
    float* out = (float*)d_out;

    float* qkv_ptr;
    cudaGetSymbolAddress((void**)&qkv_ptr, g_qkv);

    cudaFuncSetAttribute(node_gemm,
                         cudaFuncAttributeMaxDynamicSharedMemorySize, GEMM_SMEM);
    cudaFuncSetAttribute(edge_fused,
                         cudaFuncAttributeMaxDynamicSharedMemorySize, FUSED_SMEM);

    {
        dim3 grid(4, (N_NODES + 127) / 128);
        node_gemm<<<grid, 256, GEMM_SMEM>>>(nf, Wk, Wb, out, qkv_ptr);
    }
    {
        int blocks = 296;                        // 2 CTAs/SM x 148 SMs, persistent
        if (blocks > NTILES) blocks = NTILES;
        edge_fused<<<blocks, 256, FUSED_SMEM>>>(ef, Wek, Web, snd, rcv, qkv_ptr, out);
    }
}

// round 12
// speedup vs baseline: 1.3067x; 1.3067x over previous
#include <cuda_runtime.h>
#include <cuda_bf16.h>
#include <cstdint>

// ---------------------------------------------------------------------------
// ResidualGatedGCN — node tf32 GEMM + PERSISTENT fused edge GEMM/scatter
//   Persistence gives cross-tile cp.async overlap (phase C hides next tile's
//   A-chunk loads) and removes wave relaunches.
//   Phase C is R10's warp-coherent version: ep via SMEM, ld.v4 gathers, red.v4.
// ---------------------------------------------------------------------------

#define N_NODES 50000
#define N_EDGES 600000
#define NTILES  ((N_EDGES + 127) / 128)

__device__ float g_qkv[(size_t)N_NODES * 384];      // 76.8 MB

#define KC      32
#define APAD    36
#define BPAD    132
#define A_CHUNK_BYTES (128 * APAD * 4)   // 18432
#define B_BYTES       (128 * BPAD * 4)   // 67584
#define GEMM_SMEM     (B_BYTES + 2 * A_CHUNK_BYTES)        // 104448
#define FUSED_SMEM    (GEMM_SMEM + 2 * 128 * 4)

__device__ __forceinline__ uint32_t f2tf32(float f) {
    uint32_t u;
    asm("cvt.rna.tf32.f32 %0, %1;" : "=r"(u) : "f"(f));
    return u;
}
__device__ __forceinline__ void mma_tf32(float& d0, float& d1, float& d2, float& d3,
                                         uint32_t a0, uint32_t a1, uint32_t a2, uint32_t a3,
                                         uint32_t b0, uint32_t b1)
{
    asm volatile(
        "mma.sync.aligned.m16n8k8.row.col.f32.tf32.tf32.f32 "
        "{%0,%1,%2,%3}, {%4,%5,%6,%7}, {%8,%9}, {%0,%1,%2,%3};"
        : "+f"(d0), "+f"(d1), "+f"(d2), "+f"(d3)
        : "r"(a0), "r"(a1), "r"(a2), "r"(a3), "r"(b0), "r"(b1));
}
__device__ __forceinline__ uint32_t smem_u32(const void* p) {
    uint32_t a;
    asm("{ .reg .u64 t; cvta.to.shared.u64 t, %1; cvt.u32.u64 %0, t; }"
        : "=r"(a) : "l"(p));
    return a;
}
__device__ __forceinline__ uint64_t policy_evict_first() {
    uint64_t pol;
    asm("createpolicy.fractional.L2::evict_first.b64 %0, 1.0;" : "=l"(pol));
    return pol;
}
__device__ __forceinline__ uint64_t policy_evict_last() {
    uint64_t pol;
    asm("createpolicy.fractional.L2::evict_last.b64 %0, 1.0;" : "=l"(pol));
    return pol;
}
__device__ __forceinline__ void cp_async16_pol(uint32_t sdst, const void* gsrc,
                                               int bytes, uint64_t pol) {
    asm volatile("cp.async.cg.shared.global.L2::cache_hint [%0], [%1], 16, %2, %3;"
                 :: "r"(sdst), "l"(gsrc), "r"(bytes), "l"(pol));
}
__device__ __forceinline__ void cp_commit() {
    asm volatile("cp.async.commit_group;" ::: "memory");
}
__device__ __forceinline__ void cp_wait1() {
    asm volatile("cp.async.wait_group 1;" ::: "memory");
}
__device__ __forceinline__ void cp_wait0() {
    asm volatile("cp.async.wait_group 0;" ::: "memory");
}
__device__ __forceinline__ float4 ld_keep_f4(const float* p, uint64_t pol) {
    float4 v;
    asm volatile("ld.global.nc.L2::cache_hint.v4.f32 {%0,%1,%2,%3}, [%4], %5;"
                 : "=f"(v.x), "=f"(v.y), "=f"(v.z), "=f"(v.w)
                 : "l"(p), "l"(pol));
    return v;
}
__device__ __forceinline__ float sigmoidf_(float x) {
    return 1.0f / (1.0f + __expf(-x));
}
__device__ __forceinline__ void red_v4(float* p, float4 m) {
    asm volatile("red.global.add.v4.f32 [%0], {%1,%2,%3,%4};"
                 :: "l"(p), "f"(m.x), "f"(m.y), "f"(m.z), "f"(m.w));
}

struct GemmCtx { int wid, lane, g, t, wm, wn; };

// ===========================================================================
// Node GEMM (unchanged): 128x128 tile, K=128, cp.async pipeline.
// ===========================================================================
__device__ __forceinline__
void gemm_body(const float* __restrict__ A, int M, int Wstride,
               const float* __restrict__ W, int colW0,
               int row0, char* smem, const GemmCtx& cx,
               float acc[2][8][4], uint64_t pol)
{
    uint32_t* Bs = (uint32_t*)smem;
    float* Abuf[2] = { (float*)(smem + B_BYTES),
                       (float*)(smem + B_BYTES + A_CHUNK_BYTES) };
    const uint32_t sbase = smem_u32(smem);
    const uint32_t a_s[2] = { sbase + B_BYTES, sbase + B_BYTES + A_CHUNK_BYTES };
    const int tid = threadIdx.x;

    auto copyA = [&](int chunk, uint32_t sdst) {
        #pragma unroll
        for (int j = 0; j < 4; j++) {
            const int idx = tid + j * 256;
            const int r   = idx >> 3;
            const int seg = idx & 7;
            const int gr  = row0 + r;
            const int bytes = (gr < M) ? 16 : 0;
            const int grc = (gr < M) ? gr : (M - 1);
            cp_async16_pol(sdst + (r * APAD + seg * 4) * 4,
                           A + (size_t)grc * 128 + chunk * KC + seg * 4, bytes, pol);
        }
    };

    copyA(0, a_s[0]); cp_commit();

    #pragma unroll
    for (int it = 0; it < 16; it++) {
        const int idx = tid + it * 256;
        const int k   = idx >> 5;
        const int n4  = (idx & 31) * 4;
        const float4 v = *(const float4*)&W[(size_t)k * Wstride + colW0 + n4];
        uint4 o;
        o.x = f2tf32(v.x); o.y = f2tf32(v.y); o.z = f2tf32(v.z); o.w = f2tf32(v.w);
        *(uint4*)&Bs[k * BPAD + n4] = o;
    }

    copyA(1, a_s[1]); cp_commit();

    #pragma unroll
    for (int m = 0; m < 2; m++)
        #pragma unroll
        for (int n = 0; n < 8; n++)
            #pragma unroll
            for (int j = 0; j < 4; j++) acc[m][n][j] = 0.f;

    auto compute_chunk = [&](const float* __restrict__ Ab, int kb) {
        #pragma unroll
        for (int ks = 0; ks < 4; ks++) {
            const int k0 = ks * 8;
            uint32_t af[2][4];
            #pragma unroll
            for (int m = 0; m < 2; m++) {
                const int rb = cx.wm * 32 + m * 16 + cx.g;
                const float* p0 = Ab + rb * APAD + k0 + cx.t;
                const float* p1 = Ab + (rb + 8) * APAD + k0 + cx.t;
                af[m][0] = f2tf32(p0[0]);
                af[m][1] = f2tf32(p1[0]);
                af[m][2] = f2tf32(p0[4]);
                af[m][3] = f2tf32(p1[4]);
            }
            #pragma unroll
            for (int n = 0; n < 8; n++) {
                const int nidx = cx.wn * 64 + n * 8 + cx.g;
                const uint32_t b0 = Bs[(kb + k0 + cx.t) * BPAD + nidx];
                const uint32_t b1 = Bs[(kb + k0 + cx.t + 4) * BPAD + nidx];
                #pragma unroll
                for (int m = 0; m < 2; m++)
                    mma_tf32(acc[m][n][0], acc[m][n][1], acc[m][n][2], acc[m][n][3],
                             af[m][0], af[m][1], af[m][2], af[m][3], b0, b1);
            }
        }
    };

    cp_wait1(); __syncthreads();
    compute_chunk(Abuf[0], 0);
    __syncthreads(); copyA(2, a_s[0]); cp_commit();

    cp_wait1(); __syncthreads();
    compute_chunk(Abuf[1], 32);
    __syncthreads(); copyA(3, a_s[1]); cp_commit();

    cp_wait1(); __syncthreads();
    compute_chunk(Abuf[0], 64);

    cp_wait0(); __syncthreads();
    compute_chunk(Abuf[1], 96);
}

__global__ __launch_bounds__(256, 2)
void node_gemm(const float* __restrict__ nf,
               const float* __restrict__ Wk,
               const float* __restrict__ Wb,
               float* __restrict__ out,
               float* __restrict__ qkv)
{
    extern __shared__ char smem[];
    const int row0  = blockIdx.y * 128;
    const int colW0 = blockIdx.x * 128;
    const uint64_t pol = policy_evict_first();

    GemmCtx cx;
    {
        const int tid = threadIdx.x;
        cx.wid = tid >> 5; cx.lane = tid & 31;
        cx.g = cx.lane >> 2; cx.t = cx.lane & 3;
        cx.wm = cx.wid >> 1; cx.wn = cx.wid & 1;
    }
    float acc[2][8][4];
    gemm_body(nf, N_NODES, 512, Wk, colW0, row0, smem, cx, acc, pol);

    float2 bvs[8];
    #pragma unroll
    for (int n = 0; n < 8; n++)
        bvs[n] = *(const float2*)&Wb[colW0 + cx.wn * 64 + n * 8 + 2 * cx.t];

    float* C;
    int Cstride, colC0;
    if (blockIdx.x == 0) { C = out; Cstride = 128; colC0 = 0; }
    else                 { C = qkv; Cstride = 384; colC0 = colW0 - 128; }

    #pragma unroll
    for (int m = 0; m < 2; m++) {
        const int r0 = row0 + cx.wm * 32 + m * 16 + cx.g;
        const int r1 = r0 + 8;
        #pragma unroll
        for (int n = 0; n < 8; n++) {
            const int cc = colC0 + cx.wn * 64 + n * 8 + 2 * cx.t;
            if (r0 < N_NODES)
                *(float2*)&C[(size_t)r0 * Cstride + cc] =
                    make_float2(acc[m][n][0] + bvs[n].x, acc[m][n][1] + bvs[n].y);
            if (r1 < N_NODES)
                *(float2*)&C[(size_t)r1 * Cstride + cc] =
                    make_float2(acc[m][n][2] + bvs[n].x, acc[m][n][3] + bvs[n].y);
        }
    }
}

// ===========================================================================
// Persistent fused edge kernel: per tile, B re-staged (L2-hot), pipelined
// A GEMM, ep parked in SMEM (B region), R10's warp-coherent phase C.
// Next tile's chunks 0/1 are committed before phase C so its latency is
// hidden behind the gathers/reds.
// ===========================================================================
__global__ __launch_bounds__(256, 2)
void edge_fused(const float* __restrict__ ef,
                const float* __restrict__ We,
                const float* __restrict__ Web,
                const int*   __restrict__ snd,
                const int*   __restrict__ rcv,
                const float* __restrict__ qkv,
                float* __restrict__ out)
{
    extern __shared__ char smem[];
    uint32_t* Bs   = (uint32_t*)smem;                 // We (tf32) -> reused as ep_s
    float*    ep_s = (float*)smem;
    float* Abuf[2] = { (float*)(smem + B_BYTES),
                       (float*)(smem + B_BYTES + A_CHUNK_BYTES) };
    int* s_snd = (int*)(smem + GEMM_SMEM);
    int* s_rcv = (int*)(smem + GEMM_SMEM + 128 * 4);
    const uint32_t sbase = smem_u32(smem);
    const uint32_t a_s[2] = { sbase + B_BYTES, sbase + B_BYTES + A_CHUNK_BYTES };

    const int tid = threadIdx.x;
    const uint64_t pol_stream = policy_evict_first();
    const uint64_t pol_keep   = policy_evict_last();

    GemmCtx cx;
    cx.wid = tid >> 5; cx.lane = tid & 31;
    cx.g = cx.lane >> 2; cx.t = cx.lane & 3;
    cx.wm = cx.wid >> 1; cx.wn = cx.wid & 1;

    auto copyA = [&](int tile, int chunk, uint32_t sdst) {
        const int row0 = tile * 128;
        #pragma unroll
        for (int j = 0; j < 4; j++) {
            const int idx = tid + j * 256;
            const int r   = idx >> 3;
            const int seg = idx & 7;
            const int gr  = row0 + r;
            const int bytes = (gr < N_EDGES) ? 16 : 0;
            const int grc = (gr < N_EDGES) ? gr : (N_EDGES - 1);
            cp_async16_pol(sdst + (r * APAD + seg * 4) * 4,
                           ef + (size_t)grc * 128 + chunk * KC + seg * 4, bytes, pol_stream);
        }
    };

    float2 bvs[8];
    #pragma unroll
    for (int n = 0; n < 8; n++)
        bvs[n] = *(const float2*)&Web[cx.wn * 64 + n * 8 + 2 * cx.t];

    auto compute_chunk = [&](const float* __restrict__ Ab, int kb, float acc[2][8][4]) {
        #pragma unroll
        for (int ks = 0; ks < 4; ks++) {
            const int k0 = ks * 8;
            uint32_t af[2][4];
            #pragma unroll
            for (int m = 0; m < 2; m++) {
                const int rb = cx.wm * 32 + m * 16 + cx.g;
                const float* p0 = Ab + rb * APAD + k0 + cx.t;
                const float* p1 = Ab + (rb + 8) * APAD + k0 + cx.t;
                af[m][0] = f2tf32(p0[0]);
                af[m][1] = f2tf32(p1[0]);
                af[m][2] = f2tf32(p0[4]);
                af[m][3] = f2tf32(p1[4]);
            }
            #pragma unroll
            for (int n = 0; n < 8; n++) {
                const int nidx = cx.wn * 64 + n * 8 + cx.g;
                const uint32_t b0 = Bs[(kb + k0 + cx.t) * BPAD + nidx];
                const uint32_t b1 = Bs[(kb + k0 + cx.t + 4) * BPAD + nidx];
                #pragma unroll
                for (int m = 0; m < 2; m++)
                    mma_tf32(acc[m][n][0], acc[m][n][1], acc[m][n][2], acc[m][n][3],
                             af[m][0], af[m][1], af[m][2], af[m][3], b0, b1);
            }
        }
    };

    int tile = blockIdx.x;
    if (tile < NTILES) {
        copyA(tile, 0, a_s[0]); cp_commit();
        copyA(tile, 1, a_s[1]); cp_commit();
    }

    for (; tile < NTILES; tile += gridDim.x) {
        const int row0 = tile * 128;
        const int nxt  = tile + gridDim.x;
        const bool has_next = (nxt < NTILES);

        __syncthreads();    // prior phase C done: B/ep region + index tiles free

        // stage indices for this tile
        if (tid < 128) {
            const int e = row0 + tid;
            s_snd[tid] = (e < N_EDGES) ? __ldg(&snd[e]) : 0;
        } else {
            const int e = row0 + tid - 128;
            s_rcv[tid - 128] = (e < N_EDGES) ? __ldg(&rcv[e]) : 0;
        }

        // re-stage B (We) — L2-hot, overlaps outstanding A-chunk loads
        #pragma unroll
        for (int it = 0; it < 16; it++) {
            const int idx = tid + it * 256;
            const int k   = idx >> 5;
            const int n4  = (idx & 31) * 4;
            const float4 v = *(const float4*)&We[(size_t)k * 128 + n4];
            uint4 o;
            o.x = f2tf32(v.x); o.y = f2tf32(v.y); o.z = f2tf32(v.z); o.w = f2tf32(v.w);
            *(uint4*)&Bs[k * BPAD + n4] = o;
        }

        float acc[2][8][4];
        #pragma unroll
        for (int m = 0; m < 2; m++)
            #pragma unroll
            for (int n = 0; n < 8; n++)
                #pragma unroll
                for (int j = 0; j < 4; j++) acc[m][n][j] = 0.f;

        cp_wait1(); __syncthreads();          // chunk0 ready; B visible
        compute_chunk(Abuf[0], 0, acc);
        __syncthreads(); copyA(tile, 2, a_s[0]); cp_commit();

        cp_wait1(); __syncthreads();
        compute_chunk(Abuf[1], 32, acc);
        __syncthreads(); copyA(tile, 3, a_s[1]); cp_commit();

        cp_wait1(); __syncthreads();
        compute_chunk(Abuf[0], 64, acc);
        __syncthreads();
        if (has_next) { copyA(nxt, 0, a_s[0]); cp_commit(); }

        if (has_next) cp_wait1(); else cp_wait0();
        __syncthreads();
        compute_chunk(Abuf[1], 96, acc);
        __syncthreads();                       // all warps done reading Bs
        if (has_next) { copyA(nxt, 1, a_s[1]); cp_commit(); }

        // ---- park ep (+bias) into SMEM (B region dead until next tile) ----
        #pragma unroll
        for (int m = 0; m < 2; m++) {
            const int r0l = cx.wm * 32 + m * 16 + cx.g;
            #pragma unroll
            for (int n = 0; n < 8; n++) {
                const int cc = cx.wn * 64 + n * 8 + 2 * cx.t;
                *(float2*)&ep_s[r0l * BPAD + cc] =
                    make_float2(acc[m][n][0] + bvs[n].x, acc[m][n][1] + bvs[n].y);
                *(float2*)&ep_s[(r0l + 8) * BPAD + cc] =
                    make_float2(acc[m][n][2] + bvs[n].x, acc[m][n][3] + bvs[n].y);
            }
        }
        __syncthreads();

        // ---- phase C (R10): 4-edge ILP batches, warp-coherent ld.v4/red.v4;
        //      next tile's chunks 0/1 stream in behind this ----
        const int d = cx.lane * 4;
        #pragma unroll
        for (int b = 0; b < 4; b++) {
            int el[4], ss[4], rr[4];
            bool ok[4];
            #pragma unroll
            for (int i = 0; i < 4; i++) {
                el[i] = cx.wid * 16 + b * 4 + i;
                ok[i] = (row0 + el[i]) < N_EDGES;
                ss[i] = s_snd[el[i]];
                rr[i] = s_rcv[el[i]];
            }
            float4 q[4], kk[4], vv[4], epv[4];
            #pragma unroll
            for (int i = 0; i < 4; i++) {
                q[i]   = ld_keep_f4(&qkv[(size_t)rr[i] * 384 + d], pol_keep);
                kk[i]  = ld_keep_f4(&qkv[(size_t)ss[i] * 384 + 128 + d], pol_keep);
                vv[i]  = ld_keep_f4(&qkv[(size_t)ss[i] * 384 + 256 + d], pol_keep);
                epv[i] = *(const float4*)&ep_s[el[i] * BPAD + d];
            }
            #pragma unroll
            for (int i = 0; i < 4; i++) {
                float4 m;
                m.x = sigmoidf_(q[i].x + kk[i].x + epv[i].x) * vv[i].x;
                m.y = sigmoidf_(q[i].y + kk[i].y + epv[i].y) * vv[i].y;
                m.z = sigmoidf_(q[i].z + kk[i].z + epv[i].z) * vv[i].z;
                m.w = sigmoidf_(q[i].w + kk[i].w + epv[i].w) * vv[i].w;
                if (ok[i])
                    red_v4(&out[(size_t)rr[i] * 128 + d], m);
            }
        }
    }
}

// ---------------------------------------------------------------------------
// Launch
// Inputs: 0 nf[50000,128] 1 snd[600000] 2 rcv[600000] 3 ef[600000,128]
//         4 Wk[128,512] 5 Wb[512] 6 Wek[128,128] 7 Web[128]
// ---------------------------------------------------------------------------
extern "C" void kernel_launch(void* const* d_in, const int* in_sizes, int n_in,
                              void* d_out, int out_size)
{
    const float* nf   = (const float*)d_in[0];
    const int*   snd  = (const int*)  d_in[1];
    const int*   rcv  = (const int*)  d_in[2];
    const float* ef   = (const float*)d_in[3];
    const float* Wk   = (const float*)d_in[4];
    const float* Wb   = (const float*)d_in[5];
    const float* Wek  = (const float*)d_in[6];
    const float* Web  = (const float*)d_in[7];
    float* out = (float*)d_out;

    float* qkv_ptr;
    cudaGetSymbolAddress((void**)&qkv_ptr, g_qkv);

    cudaFuncSetAttribute(node_gemm,
                         cudaFuncAttributeMaxDynamicSharedMemorySize, GEMM_SMEM);
    cudaFuncSetAttribute(edge_fused,
                         cudaFuncAttributeMaxDynamicSharedMemorySize, FUSED_SMEM);

    {
        dim3 grid(4, (N_NODES + 127) / 128);
        node_gemm<<<grid, 256, GEMM_SMEM>>>(nf, Wk, Wb, out, qkv_ptr);
    }
    {
        int blocks = 296;                        // 2 CTAs/SM, persistent
        if (blocks > NTILES) blocks = NTILES;
        edge_fused<<<blocks, 256, FUSED_SMEM>>>(ef, Wek, Web, snd, rcv, qkv_ptr, out);
    }
}